// round 6
// baseline (speedup 1.0000x reference)
#include <cuda_runtime.h>
#include <cuda_bf16.h>
#include <cstdint>

#define SEQ   4096
#define HD    2048
#define NE    64
#define BATCH 2
#define NTOK  (BATCH*SEQ)
#define SW    1024
#define GATE_BLOCKS 128   // 8192 tokens / 64 per tile
#define RSH   0.02209708691207961f   // 2048^-0.5

// scratch (no cudaMalloc allowed)
__device__ int   g_gid[NTOK];
__device__ float g_inv[NTOK];

__device__ __forceinline__ bool is_vis(int m) { return (unsigned)(m - 1) <= 1u; }

// ---------------------------------------------------------------------------
// Kernel 1: blocks 0..1  -> vision group-id scan per batch row
//           blocks 2..   -> per-token inv RMS  (rsqrt(mean(x^2)+eps))
// ---------------------------------------------------------------------------
__global__ __launch_bounds__(256) void prep_kernel(const float* __restrict__ x,
                                                   const int* __restrict__ packed,
                                                   const int* __restrict__ mm)
{
    int bid = blockIdx.x, tid = threadIdx.x;
    if (bid < BATCH) {
        __shared__ int tsum[256];
        __shared__ int toff[256];
        const int* row = mm + bid * SEQ;
        int base = tid * 16;
        // pass 1: per-thread count of group starts
        int prev = (base == 0) ? 0 : (int)is_vis(row[base - 1]);
        int cnt = 0;
        #pragma unroll
        for (int i = 0; i < 16; i++) {
            int v = (int)is_vis(row[base + i]);
            cnt += (v & (prev ^ 1));
            prev = v;
        }
        tsum[tid] = cnt;
        __syncthreads();
        if (tid == 0) {
            int a = 0;
            for (int i = 0; i < 256; i++) { toff[i] = a; a += tsum[i]; }
        }
        __syncthreads();
        // pass 2: write gids
        int run = toff[tid];
        prev = (base == 0) ? 0 : (int)is_vis(row[base - 1]);
        #pragma unroll
        for (int i = 0; i < 16; i++) {
            int v = (int)is_vis(row[base + i]);
            run += (v & (prev ^ 1));
            prev = v;
            g_gid[bid * SEQ + base + i] = v ? (run - 1) : -1;
        }
    } else {
        int token = bid - BATCH;
        const float4* xr = (const float4*)(x + (size_t)token * HD);
        float s = 0.f;
        #pragma unroll
        for (int i = 0; i < 2; i++) {
            float4 v = xr[tid + i * 256];
            s += v.x * v.x + v.y * v.y + v.z * v.z + v.w * v.w;
        }
        #pragma unroll
        for (int off = 16; off; off >>= 1) s += __shfl_xor_sync(0xFFFFFFFFu, s, off);
        __shared__ float ws[8];
        if ((tid & 31) == 0) ws[tid >> 5] = s;
        __syncthreads();
        if (tid == 0) {
            float t = 0.f;
            #pragma unroll
            for (int i = 0; i < 8; i++) t += ws[i];
            g_inv[token] = rsqrtf(t * (1.0f / HD) + 1e-6f);
        }
    }
}

// ---------------------------------------------------------------------------
// Kernel 2 (fused): blocks [0,128)  -> gate GEMM + top-4 (FMA-bound)
//                   blocks [128,..) -> mask rows         (DRAM-store-bound)
// ---------------------------------------------------------------------------
__global__ __launch_bounds__(256) void fused_kernel(const float* __restrict__ x,
                                                    const int* __restrict__ packed,
                                                    const float* __restrict__ scale,
                                                    const float* __restrict__ w,
                                                    float* __restrict__ out)
{
    const int bid = blockIdx.x, tid = threadIdx.x;
    const float NEGF = __int_as_float(0xFF7FFFFF);  // -FLT_MAX = finfo(f32).min

    if (bid < GATE_BLOCKS) {
        // ================= gate: 64 tokens x 64 experts, K=2048 =================
        __shared__ float sh[4352];            // As[32][64] | Bs[32][64] ; reused as L[64][65]
        float* As = sh;                       // [k][m]
        float* Bs = sh + 2048;                // [k][e]

        const int m0 = bid * 64;
        const int tx = tid & 15, ty = tid >> 4;     // expert / token quad
        const int lt = tid >> 2;                    // 0..63 row for loads
        const int lc = tid & 3;                     // k-chunk (8 floats)
        const float inv = g_inv[m0 + lt];

        float acc[4][4];
        #pragma unroll
        for (int i = 0; i < 4; i++)
            #pragma unroll
            for (int j = 0; j < 4; j++) acc[i][j] = 0.f;

        const float4* xrow = (const float4*)(x + (size_t)(m0 + lt) * HD);
        const float4* wrow = (const float4*)(w + (size_t)lt * HD);

        for (int k0 = 0; k0 < HD; k0 += 32) {
            int kq = (k0 + lc * 8) >> 2;            // float4 index
            float4 a0 = xrow[kq],     a1 = xrow[kq + 1];
            float4 b0 = wrow[kq],     b1 = wrow[kq + 1];
            float4 s0 = ((const float4*)scale)[kq];
            float4 s1 = ((const float4*)scale)[kq + 1];
            __syncthreads();                        // prev-iter reads done
            int kk = lc * 8;
            As[(kk + 0) * 64 + lt] = a0.x * inv;
            As[(kk + 1) * 64 + lt] = a0.y * inv;
            As[(kk + 2) * 64 + lt] = a0.z * inv;
            As[(kk + 3) * 64 + lt] = a0.w * inv;
            As[(kk + 4) * 64 + lt] = a1.x * inv;
            As[(kk + 5) * 64 + lt] = a1.y * inv;
            As[(kk + 6) * 64 + lt] = a1.z * inv;
            As[(kk + 7) * 64 + lt] = a1.w * inv;
            Bs[(kk + 0) * 64 + lt] = b0.x * s0.x * RSH;
            Bs[(kk + 1) * 64 + lt] = b0.y * s0.y * RSH;
            Bs[(kk + 2) * 64 + lt] = b0.z * s0.z * RSH;
            Bs[(kk + 3) * 64 + lt] = b0.w * s0.w * RSH;
            Bs[(kk + 4) * 64 + lt] = b1.x * s1.x * RSH;
            Bs[(kk + 5) * 64 + lt] = b1.y * s1.y * RSH;
            Bs[(kk + 6) * 64 + lt] = b1.z * s1.z * RSH;
            Bs[(kk + 7) * 64 + lt] = b1.w * s1.w * RSH;
            __syncthreads();
            #pragma unroll
            for (int k = 0; k < 32; k++) {
                float4 av = *(const float4*)&As[k * 64 + ty * 4];
                float4 bv = *(const float4*)&Bs[k * 64 + tx * 4];
                float a4[4] = {av.x, av.y, av.z, av.w};
                float b4[4] = {bv.x, bv.y, bv.z, bv.w};
                #pragma unroll
                for (int i = 0; i < 4; i++)
                    #pragma unroll
                    for (int j = 0; j < 4; j++)
                        acc[i][j] = fmaf(a4[i], b4[j], acc[i][j]);
            }
        }
        __syncthreads();                            // done reading As/Bs, reuse as L
        #pragma unroll
        for (int i = 0; i < 4; i++)
            #pragma unroll
            for (int j = 0; j < 4; j++)
                sh[(ty * 4 + i) * 65 + tx * 4 + j] = acc[i][j];
        __syncthreads();

        // top-4 over raw logits; weights = exp(l-m)/sum(top4 exp) (softmax denom cancels)
        float* wout = out + (size_t)67108864;       // 2*2^25
        float* iout = out + (size_t)67141632;
        int wi = tid >> 5, lane = tid & 31;
        const float NINF = __int_as_float(0xFF800000);
        for (int r = 0; r < 8; r++) {
            int t = wi * 8 + r;
            float v0 = sh[t * 65 + lane];
            float v1 = sh[t * 65 + 32 + lane];
            float wsel[4]; int isel[4];
            #pragma unroll
            for (int k = 0; k < 4; k++) {
                float bv; int bi;
                if (v0 >= v1) { bv = v0; bi = lane; } else { bv = v1; bi = lane + 32; }
                #pragma unroll
                for (int off = 16; off; off >>= 1) {
                    float ov = __shfl_xor_sync(0xFFFFFFFFu, bv, off);
                    int   oi = __shfl_xor_sync(0xFFFFFFFFu, bi, off);
                    if (ov > bv || (ov == bv && oi < bi)) { bv = ov; bi = oi; }
                }
                wsel[k] = bv; isel[k] = bi;
                if (bi == lane) v0 = NINF;
                else if (bi == lane + 32) v1 = NINF;
            }
            if (lane == 0) {
                float m = wsel[0];
                float e0 = __expf(wsel[0] - m);
                float e1 = __expf(wsel[1] - m);
                float e2 = __expf(wsel[2] - m);
                float e3 = __expf(wsel[3] - m);
                float rs = 1.0f / (e0 + e1 + e2 + e3);
                size_t ob = (size_t)(m0 + t) * 4;
                wout[ob + 0] = e0 * rs;  iout[ob + 0] = (float)isel[0];
                wout[ob + 1] = e1 * rs;  iout[ob + 1] = (float)isel[1];
                wout[ob + 2] = e2 * rs;  iout[ob + 2] = (float)isel[2];
                wout[ob + 3] = e3 * rs;  iout[ob + 3] = (float)isel[3];
            }
        }
    } else {
        // ================= mask: one (b, q) row, write 2x 4096 floats =================
        int id = bid - GATE_BLOCKS;
        int b = id >> 12, q = id & 4095;
        const int* pr = packed + b * SEQ;
        const int* gr = g_gid + b * SEQ;
        int pq = pr[q];
        int gq = gr[q];
        bool pqv = (pq > 0);
        float* fo = out + (((size_t)b) << 24) + (((size_t)q) << 12);
        float* so = fo + ((size_t)1 << 25);

        #pragma unroll
        for (int i = 0; i < 4; i++) {
            int idx = tid + i * 256;
            int kv = idx * 4;
            int4 pk = ((const int4*)pr)[idx];
            int4 gk = ((const int4*)gr)[idx];
            float4 f, s;
            {
                bool sd = (pq == pk.x) & pqv;
                bool fl = sd & (kv <= q);
                bool sb = (fl & ((q - kv) < SW)) | ((gq == gk.x) & (gq >= 0) & sd);
                f.x = fl ? 0.f : NEGF;  s.x = sb ? 0.f : NEGF;
            }
            {
                bool sd = (pq == pk.y) & pqv;
                bool fl = sd & (kv + 1 <= q);
                bool sb = (fl & ((q - kv - 1) < SW)) | ((gq == gk.y) & (gq >= 0) & sd);
                f.y = fl ? 0.f : NEGF;  s.y = sb ? 0.f : NEGF;
            }
            {
                bool sd = (pq == pk.z) & pqv;
                bool fl = sd & (kv + 2 <= q);
                bool sb = (fl & ((q - kv - 2) < SW)) | ((gq == gk.z) & (gq >= 0) & sd);
                f.z = fl ? 0.f : NEGF;  s.z = sb ? 0.f : NEGF;
            }
            {
                bool sd = (pq == pk.w) & pqv;
                bool fl = sd & (kv + 3 <= q);
                bool sb = (fl & ((q - kv - 3) < SW)) | ((gq == gk.w) & (gq >= 0) & sd);
                f.w = fl ? 0.f : NEGF;  s.w = sb ? 0.f : NEGF;
            }
            ((float4*)fo)[idx] = f;
            ((float4*)so)[idx] = s;
        }
    }
}

// ---------------------------------------------------------------------------
// Launch: inputs per metadata order: x, packed_seq_ids, mm_token_type_ids, scale, proj_w
// Output layout (float32): full_mask[2*4096*4096] | sliding_mask[2*4096*4096]
//                          | weights[8192*4] | indices[8192*4]
// ---------------------------------------------------------------------------
extern "C" void kernel_launch(void* const* d_in, const int* in_sizes, int n_in,
                              void* d_out, int out_size)
{
    const float* x      = (const float*)d_in[0];
    const int*   packed = (const int*)  d_in[1];
    const int*   mm     = (const int*)  d_in[2];
    const float* scale  = (const float*)d_in[3];
    const float* projw  = (const float*)d_in[4];
    float* out = (float*)d_out;

    prep_kernel<<<NTOK + BATCH, 256>>>(x, packed, mm);
    fused_kernel<<<GATE_BLOCKS + NTOK, 256>>>(x, packed, scale, projw, out);
}